// round 2
// baseline (speedup 1.0000x reference)
#include <cuda_runtime.h>
#include <cuda_bf16.h>
#include <cstdint>

#define S 7
#define NB 49            // S*S cells / boxes per image
#define BATCH 4096
#define NCLS 20
#define DEPTH 30         // B*5 + C
#define NTH 64           // threads per image-block

#define K2T 256
#define TOTAL_E (BATCH * NB)      // 200704
#define CHUNK (TOTAL_E / K2T)     // 784

// Scratch (device globals: no allocation allowed)
__device__ unsigned short g_entries[TOTAL_E];
__device__ float g_ap[NCLS];
__device__ int   g_gt[NCLS];

__device__ __forceinline__ float sigm(float x) {
    return 1.0f / (1.0f + expf(-x));
}

__device__ __forceinline__ float iou_f(float ax1, float ay1, float ax2, float ay2,
                                       float bx1, float by1, float bx2, float by2) {
    float lx = fmaxf(ax1, bx1), ly = fmaxf(ay1, by1);
    float rx = fminf(ax2, bx2), ry = fminf(ay2, by2);
    float w = fmaxf(rx - lx, 0.0f), h = fmaxf(ry - ly, 0.0f);
    float inter = w * h;
    float aa = (ax2 - ax1) * (ay2 - ay1);
    float ab = (bx2 - bx1) * (by2 - by1);
    return inter / (aa + ab - inter);
}

// ---------------------------------------------------------------------------
// Kernel 1: per-image decode, sort, NMS, GT matching. One block per image.
// ---------------------------------------------------------------------------
__global__ __launch_bounds__(NTH) void k_per_image(const float* __restrict__ target,
                                                   const float* __restrict__ output) {
    int img = blockIdx.x;
    int t = threadIdx.x;

    __shared__ float sO[NB * DEPTH];
    __shared__ float sT[NB * DEPTH];
    __shared__ float uconf[NB];
    __shared__ float ubox[NB][4];
    __shared__ int   ucls[NB];
    __shared__ float sbox[NB][4];
    __shared__ float sconf[NB];
    __shared__ int   scls[NB];
    __shared__ float gbx[NB][4];
    __shared__ int   gcl[NB];
    __shared__ unsigned char gvl[NB];
    __shared__ unsigned long long supm[NB];
    __shared__ float smx[NB];
    __shared__ int   sbest[NB];
    __shared__ unsigned long long keepm;
    __shared__ unsigned char stp[NB];

    const float* op = output + (size_t)img * (NB * DEPTH);
    const float* tp_ = target + (size_t)img * (NB * DEPTH);
    #pragma unroll 4
    for (int k = t; k < NB * DEPTH; k += NTH) {
        sO[k] = op[k];
        sT[k] = tp_[k];
    }
    __syncthreads();

    // ---- decode per cell ----
    if (t < NB) {
        const float* r = sO + t * DEPTH;
        float c0 = r[4], c1 = r[9];
        int resp = (c1 > c0) ? 1 : 0;               // argmax, first index on tie
        float craw = resp ? c1 : c0;
        uconf[t] = sigm(craw);

        int cb = resp * 5;
        float x = sigm(r[cb + 0]);
        float y = sigm(r[cb + 1]);
        float w = sigm(r[cb + 2]);
        float h = sigm(r[cb + 3]);
        int iy = t / S, jx = t % S;
        float cx = (x + (float)jx) * 64.0f;
        float cy = (y + (float)iy) * 64.0f;
        float W = w * 448.0f, H = h * 448.0f;
        ubox[t][0] = cx - 0.5f * W;
        ubox[t][1] = cy - 0.5f * H;
        ubox[t][2] = cx + 0.5f * W;
        ubox[t][3] = cy + 0.5f * H;

        // pred class: argmax over raw logits (sigmoid monotone)
        int best = 0;
        float bv = r[10];
        #pragma unroll
        for (int k = 1; k < NCLS; k++) {
            float v = r[10 + k];
            if (v > bv) { bv = v; best = k; }
        }
        ucls[t] = best;

        // GT decode (raw target values)
        const float* g = sT + t * DEPTH;
        gvl[t] = (g[4] > 0.5f) ? 1 : 0;
        float gx = g[0], gy = g[1], gw = g[2], gh = g[3];
        cx = (gx + (float)jx) * 64.0f;
        cy = (gy + (float)iy) * 64.0f;
        W = gw * 448.0f; H = gh * 448.0f;
        gbx[t][0] = cx - 0.5f * W;
        gbx[t][1] = cy - 0.5f * H;
        gbx[t][2] = cx + 0.5f * W;
        gbx[t][3] = cy + 0.5f * H;

        best = 0; bv = g[10];
        #pragma unroll
        for (int k = 1; k < NCLS; k++) {
            float v = g[10 + k];
            if (v > bv) { bv = v; best = k; }
        }
        gcl[t] = best;
    }
    __syncthreads();

    // ---- stable descending sort by conf: rank = #{j : cj>ci or (cj==ci && j<i)} ----
    if (t < NB) {
        float ci = uconf[t];
        int rank = 0;
        #pragma unroll 7
        for (int j = 0; j < NB; j++) {
            float cj = uconf[j];
            rank += (cj > ci) || (cj == ci && j < t);
        }
        sbox[rank][0] = ubox[t][0];
        sbox[rank][1] = ubox[t][1];
        sbox[rank][2] = ubox[t][2];
        sbox[rank][3] = ubox[t][3];
        scls[rank] = ucls[t];
        sconf[rank] = ci;
    }
    __syncthreads();

    // ---- suppression masks + per-pred best-GT IoU ----
    if (t < NB) {
        float ax1 = sbox[t][0], ay1 = sbox[t][1], ax2 = sbox[t][2], ay2 = sbox[t][3];
        int ci = scls[t];
        unsigned long long m = 0;
        for (int j = t + 1; j < NB; j++) {
            if (scls[j] == ci) {
                float v = iou_f(ax1, ay1, ax2, ay2,
                                sbox[j][0], sbox[j][1], sbox[j][2], sbox[j][3]);
                if (v > 0.5f) m |= (1ULL << j);
            }
        }
        supm[t] = m;

        // best same-class valid GT (first-max on ties; -1 when no candidate)
        float mxv;
        int bj = 0;
        {
            float v0 = (gvl[0] && gcl[0] == ci)
                         ? iou_f(ax1, ay1, ax2, ay2, gbx[0][0], gbx[0][1], gbx[0][2], gbx[0][3])
                         : -1.0f;
            mxv = v0;
            for (int j = 1; j < NB; j++) {
                float v = (gvl[j] && gcl[j] == ci)
                            ? iou_f(ax1, ay1, ax2, ay2, gbx[j][0], gbx[j][1], gbx[j][2], gbx[j][3])
                            : -1.0f;
                if (v > mxv) { mxv = v; bj = j; }
            }
        }
        smx[t] = mxv;
        sbest[t] = bj;
    }
    __syncthreads();

    // ---- sequential NMS + greedy matching (single thread, bitmask) ----
    if (t == 0) {
        unsigned long long suppressed = 0;
        for (int i = 0; i < NB; i++) {
            if (!((suppressed >> i) & 1ULL)) suppressed |= supm[i];
        }
        unsigned long long km = ~suppressed;
        keepm = km;
        unsigned long long matched = 0;
        for (int i = 0; i < NB; i++) {
            bool vp = (((km >> i) & 1ULL) != 0ULL) && (sconf[i] > 0.5f);
            int b = sbest[i];
            bool hit = vp && (smx[i] > 0.5f) && !((matched >> b) & 1ULL);
            if (hit) matched |= (1ULL << b);
            stp[i] = hit ? 1 : 0;
        }
    }
    __syncthreads();

    // ---- emit packed entry: pcls | valid<<5 | tp<<6 | gvalid<<7 | gcls<<8 ----
    if (t < NB) {
        bool vp = (((keepm >> t) & 1ULL) != 0ULL) && (sconf[t] > 0.5f);
        unsigned v = (unsigned)scls[t]
                   | (vp ? 32u : 0u)
                   | (stp[t] ? 64u : 0u)
                   | (gvl[t] ? 128u : 0u)
                   | ((unsigned)gcl[t] << 8);
        g_entries[img * NB + t] = (unsigned short)v;
    }
}

// ---------------------------------------------------------------------------
// Kernel 2: per-class AP via two-pass segmented scan. One block per class.
// ---------------------------------------------------------------------------
__global__ __launch_bounds__(K2T) void k_ap() {
    int c = blockIdx.x;
    int t = threadIdx.x;

    __shared__ int s_tp[K2T];
    __shared__ int s_fp[K2T];
    __shared__ int s_g[K2T];
    __shared__ float s_ap[K2T];

    int base = t * CHUNK;
    int tpc = 0, fpc = 0, gtc = 0;
    for (int k = 0; k < CHUNK; k++) {
        unsigned v = g_entries[base + k];
        if (((v >> 7) & 1u) && ((int)((v >> 8) & 31u) == c)) gtc++;
        if (((v >> 5) & 1u) && ((int)(v & 31u) == c)) {
            if ((v >> 6) & 1u) tpc++; else fpc++;
        }
    }
    s_tp[t] = tpc; s_fp[t] = fpc; s_g[t] = gtc;
    __syncthreads();

    if (t == 0) {
        int aT = 0, aF = 0, aG = 0;
        for (int i = 0; i < K2T; i++) {
            int tt = s_tp[i], ff = s_fp[i], gg = s_g[i];
            s_tp[i] = aT; s_fp[i] = aF;
            aT += tt; aF += ff; aG += gg;
        }
        s_g[0] = aG;   // total GT count for this class
    }
    __syncthreads();

    float g = (float)s_g[0];
    float denr = g + 1e-6f;

    int T = s_tp[t], F = s_fp[t];
    float ap = 0.0f;
    for (int k = 0; k < CHUNK; k++) {
        int e = base + k;
        unsigned v = g_entries[e];
        if (((v >> 5) & 1u) && ((int)(v & 31u) == c)) {
            if ((v >> 6) & 1u) {
                float r_prev = (float)T / denr;
                // prepended column gives precision 1 only before global entry 0
                float p_prev = (e == 0) ? 1.0f
                                        : (float)T / ((float)(T + F) + 1e-6f);
                T += 1;
                float r = (float)T / denr;
                float p = (float)T / ((float)(T + F) + 1e-6f);
                ap += (r - r_prev) * (p + p_prev) * 0.5f;
            } else {
                F += 1;
            }
        }
    }

    s_ap[t] = ap;
    __syncthreads();
    for (int o = K2T / 2; o > 0; o >>= 1) {
        if (t < o) s_ap[t] += s_ap[t + o];
        __syncthreads();
    }
    if (t == 0) {
        g_ap[c] = s_ap[0];
        g_gt[c] = s_g[0];
    }
}

// ---------------------------------------------------------------------------
// Kernel 3: mean AP over classes with GT
// ---------------------------------------------------------------------------
__global__ void k_final(float* __restrict__ out) {
    if (threadIdx.x == 0) {
        float s = 0.0f;
        int n = 0;
        for (int c = 0; c < NCLS; c++) {
            if (g_gt[c] > 0) { s += g_ap[c]; n++; }
        }
        float nh = fmaxf((float)n, 1.0f);
        out[0] = s / nh;
    }
}

extern "C" void kernel_launch(void* const* d_in, const int* in_sizes, int n_in,
                              void* d_out, int out_size) {
    const float* target = (const float*)d_in[0];
    const float* output = (const float*)d_in[1];
    float* out = (float*)d_out;

    k_per_image<<<BATCH, NTH>>>(target, output);
    k_ap<<<NCLS, K2T>>>();
    k_final<<<1, 32>>>(out);
}

// round 3
// speedup vs baseline: 1.4141x; 1.4141x over previous
#include <cuda_runtime.h>
#include <cuda_bf16.h>
#include <cstdint>

#define S 7
#define NB 49            // S*S cells / boxes per image
#define BATCH 4096
#define NCLS 20
#define DEPTH 30         // B*5 + C
#define NTH 64

#define TOTAL_E (BATCH * NB)      // 200704
#define G 196                     // blocks for AP phase
#define EPB 1024                  // entries per AP block (196*1024 = 200704)

// Scratch (device globals: no allocation allowed)
__device__ unsigned short g_entries[TOTAL_E];
__device__ int   g_tp_part[NCLS][G];
__device__ int   g_fp_part[NCLS][G];
__device__ int   g_gt_part[NCLS][G];
__device__ float g_ap_part[NCLS][G];
__device__ int   g_gt[NCLS];

__device__ __forceinline__ float sigm(float x) {
    return 1.0f / (1.0f + expf(-x));
}

__device__ __forceinline__ float iou4(float4 a, float4 b) {
    float lx = fmaxf(a.x, b.x), ly = fmaxf(a.y, b.y);
    float rx = fminf(a.z, b.z), ry = fminf(a.w, b.w);
    float w = fmaxf(rx - lx, 0.0f), h = fmaxf(ry - ly, 0.0f);
    float inter = w * h;
    float aa = (a.z - a.x) * (a.w - a.y);
    float ab = (b.z - b.x) * (b.w - b.y);
    return inter / (aa + ab - inter);
}

// ---------------------------------------------------------------------------
// Kernel 1: per-image decode, sort, NMS, GT matching. One block per image.
// ---------------------------------------------------------------------------
__global__ __launch_bounds__(NTH) void k_per_image(const float* __restrict__ target,
                                                   const float* __restrict__ output) {
    int img = blockIdx.x;
    int t = threadIdx.x;

    __shared__ float  uconf[NB];
    __shared__ float4 ubox[NB];
    __shared__ int    ucls[NB];
    __shared__ float4 sbox[NB];
    __shared__ float  sconf[NB];
    __shared__ int    scls[NB];
    __shared__ float4 gbx[NB];
    __shared__ int    gcl[NB];
    __shared__ unsigned char gvl[NB];
    __shared__ unsigned long long gmask[NCLS];   // GT membership per class (cell space)
    __shared__ unsigned long long pmask[NCLS];   // pred membership per class (sorted space)
    __shared__ unsigned long long supm[NB];
    __shared__ float smx[NB];
    __shared__ int   sbest[NB];
    __shared__ unsigned long long keepm_s;
    __shared__ unsigned char stp[NB];

    if (t < NCLS) { gmask[t] = 0ULL; pmask[t] = 0ULL; }
    __syncthreads();

    // ---- phase 1: decode directly from global (each thread owns one cell) ----
    if (t < NB) {
        const float* r = output + ((size_t)img * NB + t) * DEPTH;
        const float* g = target + ((size_t)img * NB + t) * DEPTH;

        float c0 = __ldg(r + 4), c1 = __ldg(r + 9);
        int resp = (c1 > c0) ? 1 : 0;
        float craw = resp ? c1 : c0;
        int cb = resp * 5;

        float x = sigm(__ldg(r + cb + 0));
        float y = sigm(__ldg(r + cb + 1));
        float w = sigm(__ldg(r + cb + 2));
        float h = sigm(__ldg(r + cb + 3));

        int iy = t / S, jx = t - iy * S;
        float cx = (x + (float)jx) * 64.0f;
        float cy = (y + (float)iy) * 64.0f;
        float W = w * 448.0f, H = h * 448.0f;
        ubox[t] = make_float4(cx - 0.5f * W, cy - 0.5f * H, cx + 0.5f * W, cy + 0.5f * H);
        uconf[t] = sigm(craw);

        // pred class argmax over raw logits (sigmoid monotone; first-max on ties)
        int ci = 0;
        float bv = __ldg(r + 10);
        #pragma unroll
        for (int k = 1; k < NCLS; k++) {
            float v = __ldg(r + 10 + k);
            if (v > bv) { bv = v; ci = k; }
        }
        ucls[t] = ci;

        // GT decode
        float gconf = __ldg(g + 4);
        gvl[t] = (gconf > 0.5f) ? 1 : 0;
        float gx = __ldg(g + 0), gy = __ldg(g + 1);
        float gw = __ldg(g + 2), gh = __ldg(g + 3);
        cx = (gx + (float)jx) * 64.0f;
        cy = (gy + (float)iy) * 64.0f;
        W = gw * 448.0f; H = gh * 448.0f;
        gbx[t] = make_float4(cx - 0.5f * W, cy - 0.5f * H, cx + 0.5f * W, cy + 0.5f * H);

        int gi = 0;
        bv = __ldg(g + 10);
        #pragma unroll
        for (int k = 1; k < NCLS; k++) {
            float v = __ldg(g + 10 + k);
            if (v > bv) { bv = v; gi = k; }
        }
        gcl[t] = gi;
        if (gconf > 0.5f) atomicOr(&gmask[gi], 1ULL << t);
    }
    __syncthreads();

    // ---- phase 2: stable descending rank-sort + per-class pred masks ----
    if (t < NB) {
        float ci_c = uconf[t];
        int rank = 0;
        #pragma unroll 7
        for (int j = 0; j < NB; j++) {
            float cj = uconf[j];
            rank += (cj > ci_c) || (cj == ci_c && j < t);
        }
        sbox[rank] = ubox[t];
        scls[rank] = ucls[t];
        sconf[rank] = ci_c;
        atomicOr(&pmask[ucls[t]], 1ULL << rank);
    }
    __syncthreads();

    // ---- phase 3: suppression masks + best-GT via class bitmasks ----
    if (t < NB) {
        float4 a = sbox[t];
        int ci = scls[t];

        unsigned long long m = 0;
        unsigned long long cand = pmask[ci] & (~0ULL << (t + 1));   // t<=48
        while (cand) {
            int j = __ffsll((long long)cand) - 1;
            cand &= cand - 1;
            if (iou4(a, sbox[j]) > 0.5f) m |= (1ULL << j);
        }
        supm[t] = m;

        float mxv = -1.0f;
        int bj = 0;
        unsigned long long gm = gmask[ci];
        while (gm) {
            int j = __ffsll((long long)gm) - 1;
            gm &= gm - 1;
            float v = iou4(a, gbx[j]);
            if (v > mxv) { mxv = v; bj = j; }
        }
        smx[t] = mxv;
        sbest[t] = bj;
    }
    __syncthreads();

    // ---- phase 4: sequential NMS + greedy matching (thread 0, bitmask) ----
    if (t == 0) {
        unsigned long long suppressed = 0;
        #pragma unroll 7
        for (int i = 0; i < NB; i++) {
            if (!((suppressed >> i) & 1ULL)) suppressed |= supm[i];
        }
        unsigned long long km = ~suppressed;
        keepm_s = km;
        unsigned long long matched = 0;
        for (int i = 0; i < NB; i++) {
            bool vp = (((km >> i) & 1ULL) != 0ULL) && (sconf[i] > 0.5f);
            int b = sbest[i];
            bool hit = vp && (smx[i] > 0.5f) && !((matched >> b) & 1ULL);
            if (hit) matched |= (1ULL << b);
            stp[i] = hit ? 1 : 0;
        }
    }
    __syncthreads();

    // ---- phase 5: emit packed entry ----
    if (t < NB) {
        bool vp = (((keepm_s >> t) & 1ULL) != 0ULL) && (sconf[t] > 0.5f);
        unsigned v = (unsigned)scls[t]
                   | (vp ? 32u : 0u)
                   | (stp[t] ? 64u : 0u)
                   | (gvl[t] ? 128u : 0u)
                   | ((unsigned)gcl[t] << 8);
        g_entries[img * NB + t] = (unsigned short)v;
    }
}

// ---------------------------------------------------------------------------
// Kernel 2a: per-(block, class) counts. 196 blocks, coalesced ushort4 loads.
// ---------------------------------------------------------------------------
__global__ __launch_bounds__(256) void k_count() {
    int b = blockIdx.x, t = threadIdx.x;
    __shared__ int s_tp[NCLS], s_fp[NCLS], s_gt[NCLS];
    if (t < NCLS) { s_tp[t] = 0; s_fp[t] = 0; s_gt[t] = 0; }
    __syncthreads();

    ushort4 v4 = *(const ushort4*)(g_entries + b * EPB + t * 4);
    unsigned vs[4] = {v4.x, v4.y, v4.z, v4.w};
    #pragma unroll
    for (int i = 0; i < 4; i++) {
        unsigned v = vs[i];
        if (v & 128u) atomicAdd(&s_gt[(v >> 8) & 31u], 1);
        if (v & 32u) {
            if (v & 64u) atomicAdd(&s_tp[v & 31u], 1);
            else         atomicAdd(&s_fp[v & 31u], 1);
        }
    }
    __syncthreads();

    if (t < NCLS) {
        g_tp_part[t][b] = s_tp[t];
        g_fp_part[t][b] = s_fp[t];
        g_gt_part[t][b] = s_gt[t];
    }
}

// ---------------------------------------------------------------------------
// Kernel 2b: exclusive prefix over block partials per class (in place).
// ---------------------------------------------------------------------------
__global__ void k_scan() {
    int t = threadIdx.x;
    if (t < NCLS * 3) {
        int c = t / 3, j = t % 3;
        int* arr = (j == 0) ? g_tp_part[c] : (j == 1) ? g_fp_part[c] : g_gt_part[c];
        int acc = 0;
        for (int b = 0; b < G; b++) {
            int x = arr[b];
            arr[b] = acc;
            acc += x;
        }
        if (j == 2) g_gt[c] = acc;
    }
}

// ---------------------------------------------------------------------------
// Kernel 2c: per-block AP contributions with correct starting prefixes.
// 20 class-threads walk 1024 smem-staged entries (broadcast reads).
// ---------------------------------------------------------------------------
__global__ __launch_bounds__(32) void k_apfinal() {
    int b = blockIdx.x, t = threadIdx.x;
    __shared__ unsigned short se[EPB];

    const unsigned* src = (const unsigned*)(g_entries + b * EPB);
    unsigned* d = (unsigned*)se;
    #pragma unroll
    for (int k = t; k < EPB / 2; k += 32) d[k] = src[k];
    __syncthreads();

    if (t < NCLS) {
        int c = t;
        int T = g_tp_part[c][b];
        int F = g_fp_part[c][b];
        float denr = (float)g_gt[c] + 1e-6f;
        float ap = 0.0f;
        int ebase = b * EPB;
        #pragma unroll 4
        for (int k = 0; k < EPB; k++) {
            unsigned v = se[k];
            if ((v & 32u) && (int)(v & 31u) == c) {
                if (v & 64u) {
                    float r_prev = (float)T / denr;
                    float p_prev = (ebase + k == 0)
                                     ? 1.0f
                                     : (float)T / ((float)(T + F) + 1e-6f);
                    T += 1;
                    float r = (float)T / denr;
                    float p = (float)T / ((float)(T + F) + 1e-6f);
                    ap += (r - r_prev) * (p + p_prev) * 0.5f;
                } else {
                    F += 1;
                }
            }
        }
        g_ap_part[c][b] = ap;
    }
}

// ---------------------------------------------------------------------------
// Kernel 3: deterministic reduction + mean over classes with GT
// ---------------------------------------------------------------------------
__global__ void k_final(float* __restrict__ out) {
    int t = threadIdx.x;
    __shared__ float aps[NCLS];
    if (t < NCLS) {
        float s = 0.0f;
        #pragma unroll 4
        for (int b = 0; b < G; b++) s += g_ap_part[t][b];
        aps[t] = s;
    }
    __syncthreads();
    if (t == 0) {
        float s = 0.0f;
        int n = 0;
        for (int c = 0; c < NCLS; c++) {
            if (g_gt[c] > 0) { s += aps[c]; n++; }
        }
        out[0] = s / fmaxf((float)n, 1.0f);
    }
}

extern "C" void kernel_launch(void* const* d_in, const int* in_sizes, int n_in,
                              void* d_out, int out_size) {
    const float* target = (const float*)d_in[0];
    const float* output = (const float*)d_in[1];
    float* out = (float*)d_out;

    k_per_image<<<BATCH, NTH>>>(target, output);
    k_count<<<G, 256>>>();
    k_scan<<<1, 64>>>();
    k_apfinal<<<G, 32>>>();
    k_final<<<1, 32>>>(out);
}

// round 5
// speedup vs baseline: 2.7107x; 1.9169x over previous
#include <cuda_runtime.h>
#include <cuda_bf16.h>
#include <cstdint>

#define S 7
#define NB 49            // S*S cells / boxes per image
#define BATCH 4096
#define NCLS 20
#define DEPTH 30         // B*5 + C
#define NTH 64

#define TOTAL_E (BATCH * NB)      // 200704
#define G 196                     // blocks for AP phase
#define EPB 1024                  // entries per AP block (196*1024 = 200704)
#define NSEG 32                   // 32-entry segments per AP block

// Scratch (device globals: no allocation allowed)
__device__ unsigned short g_entries[TOTAL_E];
__device__ int   g_tp_part[NCLS][G];
__device__ int   g_fp_part[NCLS][G];
__device__ int   g_gt_part[NCLS][G];
__device__ float g_ap_blk[G];
__device__ int   g_gt[NCLS];

__device__ __forceinline__ float sigm(float x) {
    return 1.0f / (1.0f + expf(-x));
}

__device__ __forceinline__ float iou4(float4 a, float4 b) {
    float lx = fmaxf(a.x, b.x), ly = fmaxf(a.y, b.y);
    float rx = fminf(a.z, b.z), ry = fminf(a.w, b.w);
    float w = fmaxf(rx - lx, 0.0f), h = fmaxf(ry - ly, 0.0f);
    float inter = w * h;
    float aa = (a.z - a.x) * (a.w - a.y);
    float ab = (b.z - b.x) * (b.w - b.y);
    return inter / (aa + ab - inter);
}

// ---------------------------------------------------------------------------
// Kernel 1: per-image decode, sort, NMS, GT matching. One block per image.
// ---------------------------------------------------------------------------
__global__ __launch_bounds__(NTH) void k_per_image(const float* __restrict__ target,
                                                   const float* __restrict__ output) {
    int img = blockIdx.x;
    int t = threadIdx.x;

    __shared__ float  uconf[NB];
    __shared__ float4 ubox[NB];
    __shared__ int    ucls[NB];
    __shared__ float4 sbox[NB];
    __shared__ float  sconf[NB];
    __shared__ int    scls[NB];
    __shared__ float4 gbx[NB];
    __shared__ int    gcl[NB];
    __shared__ unsigned char gvl[NB];
    __shared__ unsigned long long gmask[NCLS];   // GT membership per class (cell space)
    __shared__ unsigned long long pmask[NCLS];   // pred membership per class (sorted space)
    __shared__ unsigned long long supm[NB];
    __shared__ float smx[NB];
    __shared__ int   sbest[NB];
    __shared__ unsigned long long keepm_s;
    __shared__ unsigned char stp[NB];

    if (t < NCLS) { gmask[t] = 0ULL; pmask[t] = 0ULL; }
    __syncthreads();

    // ---- phase 1: decode directly from global (each thread owns one cell) ----
    if (t < NB) {
        const float* r = output + ((size_t)img * NB + t) * DEPTH;
        const float* g = target + ((size_t)img * NB + t) * DEPTH;

        float c0 = __ldg(r + 4), c1 = __ldg(r + 9);
        int resp = (c1 > c0) ? 1 : 0;
        float craw = resp ? c1 : c0;
        int cb = resp * 5;

        float x = sigm(__ldg(r + cb + 0));
        float y = sigm(__ldg(r + cb + 1));
        float w = sigm(__ldg(r + cb + 2));
        float h = sigm(__ldg(r + cb + 3));

        int iy = t / S, jx = t - iy * S;
        float cx = (x + (float)jx) * 64.0f;
        float cy = (y + (float)iy) * 64.0f;
        float W = w * 448.0f, H = h * 448.0f;
        ubox[t] = make_float4(cx - 0.5f * W, cy - 0.5f * H, cx + 0.5f * W, cy + 0.5f * H);
        uconf[t] = sigm(craw);

        // pred class argmax over raw logits (sigmoid monotone; first-max on ties)
        int ci = 0;
        float bv = __ldg(r + 10);
        #pragma unroll
        for (int k = 1; k < NCLS; k++) {
            float v = __ldg(r + 10 + k);
            if (v > bv) { bv = v; ci = k; }
        }
        ucls[t] = ci;

        // GT decode
        float gconf = __ldg(g + 4);
        gvl[t] = (gconf > 0.5f) ? 1 : 0;
        float gx = __ldg(g + 0), gy = __ldg(g + 1);
        float gw = __ldg(g + 2), gh = __ldg(g + 3);
        cx = (gx + (float)jx) * 64.0f;
        cy = (gy + (float)iy) * 64.0f;
        W = gw * 448.0f; H = gh * 448.0f;
        gbx[t] = make_float4(cx - 0.5f * W, cy - 0.5f * H, cx + 0.5f * W, cy + 0.5f * H);

        int gi = 0;
        bv = __ldg(g + 10);
        #pragma unroll
        for (int k = 1; k < NCLS; k++) {
            float v = __ldg(g + 10 + k);
            if (v > bv) { bv = v; gi = k; }
        }
        gcl[t] = gi;
        if (gconf > 0.5f) atomicOr(&gmask[gi], 1ULL << t);
    }
    __syncthreads();

    // ---- phase 2: stable descending rank-sort + per-class pred masks ----
    if (t < NB) {
        float ci_c = uconf[t];
        int rank = 0;
        #pragma unroll 7
        for (int j = 0; j < NB; j++) {
            float cj = uconf[j];
            rank += (cj > ci_c) || (cj == ci_c && j < t);
        }
        sbox[rank] = ubox[t];
        scls[rank] = ucls[t];
        sconf[rank] = ci_c;
        atomicOr(&pmask[ucls[t]], 1ULL << rank);
    }
    __syncthreads();

    // ---- phase 3: suppression masks + best-GT via class bitmasks ----
    if (t < NB) {
        float4 a = sbox[t];
        int ci = scls[t];

        unsigned long long m = 0;
        unsigned long long cand = pmask[ci] & (~0ULL << (t + 1));   // t<=48
        while (cand) {
            int j = __ffsll((long long)cand) - 1;
            cand &= cand - 1;
            if (iou4(a, sbox[j]) > 0.5f) m |= (1ULL << j);
        }
        supm[t] = m;

        float mxv = -1.0f;
        int bj = 0;
        unsigned long long gm = gmask[ci];
        while (gm) {
            int j = __ffsll((long long)gm) - 1;
            gm &= gm - 1;
            float v = iou4(a, gbx[j]);
            if (v > mxv) { mxv = v; bj = j; }
        }
        smx[t] = mxv;
        sbest[t] = bj;
    }
    __syncthreads();

    // ---- phase 4: sequential NMS + greedy matching (thread 0, bitmask) ----
    if (t == 0) {
        unsigned long long suppressed = 0;
        #pragma unroll 7
        for (int i = 0; i < NB; i++) {
            if (!((suppressed >> i) & 1ULL)) suppressed |= supm[i];
        }
        unsigned long long km = ~suppressed;
        keepm_s = km;
        unsigned long long matched = 0;
        for (int i = 0; i < NB; i++) {
            bool vp = (((km >> i) & 1ULL) != 0ULL) && (sconf[i] > 0.5f);
            int b = sbest[i];
            bool hit = vp && (smx[i] > 0.5f) && !((matched >> b) & 1ULL);
            if (hit) matched |= (1ULL << b);
            stp[i] = hit ? 1 : 0;
        }
    }
    __syncthreads();

    // ---- phase 5: emit packed entry ----
    if (t < NB) {
        bool vp = (((keepm_s >> t) & 1ULL) != 0ULL) && (sconf[t] > 0.5f);
        unsigned v = (unsigned)scls[t]
                   | (vp ? 32u : 0u)
                   | (stp[t] ? 64u : 0u)
                   | (gvl[t] ? 128u : 0u)
                   | ((unsigned)gcl[t] << 8);
        g_entries[img * NB + t] = (unsigned short)v;
    }
}

// ---------------------------------------------------------------------------
// Kernel 2a: per-(block, class) counts. 196 blocks, coalesced ushort4 loads.
// ---------------------------------------------------------------------------
__global__ __launch_bounds__(256) void k_count() {
    int b = blockIdx.x, t = threadIdx.x;
    __shared__ int s_tp[NCLS], s_fp[NCLS], s_gt[NCLS];
    if (t < NCLS) { s_tp[t] = 0; s_fp[t] = 0; s_gt[t] = 0; }
    __syncthreads();

    ushort4 v4 = *(const ushort4*)(g_entries + b * EPB + t * 4);
    unsigned vs[4] = {v4.x, v4.y, v4.z, v4.w};
    #pragma unroll
    for (int i = 0; i < 4; i++) {
        unsigned v = vs[i];
        if (v & 128u) atomicAdd(&s_gt[(v >> 8) & 31u], 1);
        if (v & 32u) {
            if (v & 64u) atomicAdd(&s_tp[v & 31u], 1);
            else         atomicAdd(&s_fp[v & 31u], 1);
        }
    }
    __syncthreads();

    if (t < NCLS) {
        g_tp_part[t][b] = s_tp[t];
        g_fp_part[t][b] = s_fp[t];
        g_gt_part[t][b] = s_gt[t];
    }
}

// ---------------------------------------------------------------------------
// Kernel 2b: exclusive prefix over block partials per class (in place).
// ---------------------------------------------------------------------------
__global__ void k_scan() {
    int t = threadIdx.x;
    if (t < NCLS * 3) {
        int c = t / 3, j = t % 3;
        int* arr = (j == 0) ? g_tp_part[c] : (j == 1) ? g_fp_part[c] : g_gt_part[c];
        int acc = 0;
        for (int b = 0; b < G; b++) {
            int x = arr[b];
            arr[b] = acc;
            acc += x;
        }
        if (j == 2) g_gt[c] = acc;
    }
}

// ---------------------------------------------------------------------------
// Kernel 2c: per-block AP contributions, fully parallel.
// Hierarchical per-class prefix: block prefix (g_*_part) + segment prefix
// (smem scan over 32 segments) + within-segment prefix (match_any/ballot).
// Each TP's trapezoid term is independent given its (T,F) prefix; all
// contributions belong to classes with GT>0, so we sum one scalar per block.
// ---------------------------------------------------------------------------
__global__ __launch_bounds__(256) void k_apfinal() {
    int b = blockIdx.x, t = threadIdx.x;
    int lane = t & 31, w = t >> 5;

    __shared__ unsigned short se[EPB];
    __shared__ int s_tpc[NSEG][NCLS];
    __shared__ int s_fpc[NSEG][NCLS];
    __shared__ float s_wsum[8];

    // stage entries (coalesced: 512 uints)
    {
        const unsigned* src = (const unsigned*)(g_entries + b * EPB);
        unsigned* d = (unsigned*)se;
        d[t] = src[t];
        d[t + 256] = src[t + 256];
    }
    // zero segment counters (32*20*2 = 1280 ints)
    {
        int* z = &s_tpc[0][0];
        #pragma unroll
        for (int k = t; k < NSEG * NCLS * 2; k += 256) z[k] = 0;
    }
    __syncthreads();

    // Phase A: per-segment per-class counts (4 entries/thread, smem atomics)
    #pragma unroll
    for (int i = 0; i < 4; i++) {
        int e = t * 4 + i;
        unsigned v = se[e];
        if (v & 32u) {
            int s = e >> 5;
            int c = v & 31u;
            if (v & 64u) atomicAdd(&s_tpc[s][c], 1);
            else         atomicAdd(&s_fpc[s][c], 1);
        }
    }
    __syncthreads();

    // Phase B: exclusive scan over segments per class (40 threads, serial 32)
    if (t < NCLS * 2) {
        int c = t % NCLS;
        int* col0 = (t < NCLS) ? &s_tpc[0][c] : &s_fpc[0][c];
        int acc = 0;
        #pragma unroll
        for (int s = 0; s < NSEG; s++) {
            int* p = col0 + s * NCLS;
            int x = *p;
            *p = acc;
            acc += x;
        }
    }
    __syncthreads();

    // Phase C: each warp handles 4 segments; within-segment prefix via match/ballot
    float acc = 0.0f;
    #pragma unroll
    for (int r = 0; r < 4; r++) {
        int s = w * 4 + r;
        unsigned v = se[s * 32 + lane];
        bool valid = (v & 32u) != 0;
        int c = v & 31u;
        bool tp = (v & 64u) != 0;
        unsigned cc = valid ? (unsigned)c : 255u;
        unsigned peers = __match_any_sync(0xffffffffu, cc);
        unsigned tpb = __ballot_sync(0xffffffffu, tp);
        if (tp) {
            unsigned ltm = (1u << lane) - 1u;
            int Tw = __popc(peers & tpb & ltm);
            int Fw = __popc(peers & ltm) - Tw;          // peers are all valid lanes
            int T = g_tp_part[c][b] + s_tpc[s][c] + Tw;
            int F = g_fp_part[c][b] + s_fpc[s][c] + Fw;
            float denr = (float)g_gt[c] + 1e-6f;
            bool first = (b == 0) && (s == 0) && (lane == 0);
            float p_prev = first ? 1.0f
                                 : (float)T / ((float)(T + F) + 1e-6f);
            float p_new = (float)(T + 1) / ((float)(T + 1 + F) + 1e-6f);
            acc += (1.0f / denr) * 0.5f * (p_prev + p_new);
        }
    }

    // warp reduce, then block reduce (deterministic fixed order)
    #pragma unroll
    for (int o = 16; o > 0; o >>= 1)
        acc += __shfl_xor_sync(0xffffffffu, acc, o);
    if (lane == 0) s_wsum[w] = acc;
    __syncthreads();
    if (t == 0) {
        float s = 0.0f;
        #pragma unroll
        for (int i = 0; i < 8; i++) s += s_wsum[i];
        g_ap_blk[b] = s;
    }
}

// ---------------------------------------------------------------------------
// Kernel 3: deterministic reduction + divide by #classes-with-GT
// ---------------------------------------------------------------------------
__global__ __launch_bounds__(256) void k_final(float* __restrict__ out) {
    int t = threadIdx.x;
    __shared__ float sv[256];
    sv[t] = (t < G) ? g_ap_blk[t] : 0.0f;
    __syncthreads();
    for (int o = 128; o > 0; o >>= 1) {
        if (t < o) sv[t] += sv[t + o];
        __syncthreads();
    }
    if (t == 0) {
        int n = 0;
        #pragma unroll
        for (int c = 0; c < NCLS; c++) n += (g_gt[c] > 0);
        out[0] = sv[0] / fmaxf((float)n, 1.0f);
    }
}

extern "C" void kernel_launch(void* const* d_in, const int* in_sizes, int n_in,
                              void* d_out, int out_size) {
    const float* target = (const float*)d_in[0];
    const float* output = (const float*)d_in[1];
    float* out = (float*)d_out;

    k_per_image<<<BATCH, NTH>>>(target, output);
    k_count<<<G, 256>>>();
    k_scan<<<1, 64>>>();
    k_apfinal<<<G, 256>>>();
    k_final<<<1, 256>>>(out);
}

// round 6
// speedup vs baseline: 3.8715x; 1.4282x over previous
#include <cuda_runtime.h>
#include <cuda_bf16.h>
#include <cstdint>

#define S 7
#define NB 49            // S*S cells / boxes per image
#define BATCH 4096
#define NCLS 20
#define DEPTH 30         // B*5 + C
#define NTH 64

#define TOTAL_E (BATCH * NB)      // 200704
#define IMG_PER_BLK 32
#define G 128                     // AP blocks (4096/32)
#define EPB 1568                  // entries per AP block (32 images * 49)
#define NSEG 49                   // 32-entry segments per AP block

// Scratch (device globals; zero-initialized at module load, re-zeroed by k_final)
__device__ unsigned short g_entries[TOTAL_E];
__device__ int   g_tp_part[NCLS][G];
__device__ int   g_fp_part[NCLS][G];
__device__ float g_ap_blk[G];
__device__ int   g_gt[NCLS];

__device__ __forceinline__ float sigm(float x) {
    return 1.0f / (1.0f + expf(-x));
}

__device__ __forceinline__ float iou4(float4 a, float4 b) {
    float lx = fmaxf(a.x, b.x), ly = fmaxf(a.y, b.y);
    float rx = fminf(a.z, b.z), ry = fminf(a.w, b.w);
    float w = fmaxf(rx - lx, 0.0f), h = fmaxf(ry - ly, 0.0f);
    float inter = w * h;
    float aa = (a.z - a.x) * (a.w - a.y);
    float ab = (b.z - b.x) * (b.w - b.y);
    return inter / (aa + ab - inter);
}

// Working arrays overlaid on the staging buffer after decode completes.
struct Work {
    float4 ubox[NB];
    float4 gbx[NB];
    float4 sbox[NB];
    unsigned long long supm[NB];
    float uconf[NB];
    float sconf[NB];
    float smx[NB];
    int   ucls[NB];
    int   scls[NB];
    int   sbest[NB];
    int   gcl[NB];
    unsigned char gvl[NB];
    unsigned char stp[NB];
};

// ---------------------------------------------------------------------------
// Kernel 1: per-image decode, sort, NMS, GT matching + count accumulation.
// One block per image; coalesced staging of input rows; smem buffer reused.
// ---------------------------------------------------------------------------
__global__ __launch_bounds__(NTH) void k_per_image(const float* __restrict__ target,
                                                   const float* __restrict__ output) {
    int img = blockIdx.x;
    int t = threadIdx.x;

    __shared__ __align__(16) float sbuf[1472];   // 5888 B staging, >= sizeof(Work)
    __shared__ unsigned long long gmask[NCLS];
    __shared__ unsigned long long pmask[NCLS];
    __shared__ int cnt_tp[NCLS], cnt_fp[NCLS], cnt_gt[NCLS];
    __shared__ unsigned long long keepm_s;

    if (t < NCLS) {
        gmask[t] = 0ULL; pmask[t] = 0ULL;
        cnt_tp[t] = 0; cnt_fp[t] = 0; cnt_gt[t] = 0;
    }

    // ---- stage pred tensor (coalesced float2) ----
    {
        const float2* src = (const float2*)(output + (size_t)img * (NB * DEPTH));
        float2* dst = (float2*)sbuf;
        #pragma unroll 4
        for (int k = t; k < NB * DEPTH / 2; k += NTH) dst[k] = src[k];
    }
    __syncthreads();

    // ---- decode preds into registers ----
    float4 p_box = make_float4(0.f, 0.f, 0.f, 0.f);
    float  p_conf = 0.f;
    int    p_cls = 0;
    int iy = t / S, jx = t - iy * S;
    if (t < NB) {
        const float* r = sbuf + t * DEPTH;
        float c0 = r[4], c1 = r[9];
        int resp = (c1 > c0) ? 1 : 0;
        float craw = resp ? c1 : c0;
        int cb = resp * 5;
        float x = sigm(r[cb + 0]);
        float y = sigm(r[cb + 1]);
        float w = sigm(r[cb + 2]);
        float h = sigm(r[cb + 3]);
        float cx = (x + (float)jx) * 64.0f;
        float cy = (y + (float)iy) * 64.0f;
        float W = w * 448.0f, H = h * 448.0f;
        p_box = make_float4(cx - 0.5f * W, cy - 0.5f * H, cx + 0.5f * W, cy + 0.5f * H);
        p_conf = sigm(craw);
        float bv = r[10];
        #pragma unroll
        for (int k = 1; k < NCLS; k++) {
            float v = r[10 + k];
            if (v > bv) { bv = v; p_cls = k; }
        }
    }
    __syncthreads();   // everyone done reading pred stage

    // ---- stage GT tensor over same buffer ----
    {
        const float2* src = (const float2*)(target + (size_t)img * (NB * DEPTH));
        float2* dst = (float2*)sbuf;
        #pragma unroll 4
        for (int k = t; k < NB * DEPTH / 2; k += NTH) dst[k] = src[k];
    }
    __syncthreads();

    // ---- decode GT into registers ----
    float4 g_box = make_float4(0.f, 0.f, 0.f, 0.f);
    int g_cls = 0, g_valid = 0;
    if (t < NB) {
        const float* g = sbuf + t * DEPTH;
        g_valid = (g[4] > 0.5f) ? 1 : 0;
        float cx = (g[0] + (float)jx) * 64.0f;
        float cy = (g[1] + (float)iy) * 64.0f;
        float W = g[2] * 448.0f, H = g[3] * 448.0f;
        g_box = make_float4(cx - 0.5f * W, cy - 0.5f * H, cx + 0.5f * W, cy + 0.5f * H);
        float bv = g[10];
        #pragma unroll
        for (int k = 1; k < NCLS; k++) {
            float v = g[10 + k];
            if (v > bv) { bv = v; g_cls = k; }
        }
    }
    __syncthreads();   // everyone done reading GT stage -> safe to overlay

    Work* Wk = (Work*)sbuf;
    if (t < NB) {
        Wk->ubox[t] = p_box;
        Wk->uconf[t] = p_conf;
        Wk->ucls[t] = p_cls;
        Wk->gbx[t] = g_box;
        Wk->gcl[t] = g_cls;
        Wk->gvl[t] = (unsigned char)g_valid;
        if (g_valid) {
            atomicOr(&gmask[g_cls], 1ULL << t);
            atomicAdd(&cnt_gt[g_cls], 1);
        }
    }
    __syncthreads();

    // ---- stable descending rank-sort + per-class pred masks ----
    if (t < NB) {
        float ci_c = Wk->uconf[t];
        int rank = 0;
        #pragma unroll 7
        for (int j = 0; j < NB; j++) {
            float cj = Wk->uconf[j];
            rank += (cj > ci_c) || (cj == ci_c && j < t);
        }
        Wk->sbox[rank] = Wk->ubox[t];
        Wk->scls[rank] = Wk->ucls[t];
        Wk->sconf[rank] = ci_c;
        atomicOr(&pmask[Wk->ucls[t]], 1ULL << rank);
    }
    __syncthreads();

    // ---- suppression masks + best-GT via class bitmasks ----
    if (t < NB) {
        float4 a = Wk->sbox[t];
        int ci = Wk->scls[t];

        unsigned long long m = 0;
        unsigned long long cand = pmask[ci] & (~0ULL << (t + 1));   // t<=48
        while (cand) {
            int j = __ffsll((long long)cand) - 1;
            cand &= cand - 1;
            if (iou4(a, Wk->sbox[j]) > 0.5f) m |= (1ULL << j);
        }
        Wk->supm[t] = m;

        float mxv = -1.0f;
        int bj = 0;
        unsigned long long gm = gmask[ci];
        while (gm) {
            int j = __ffsll((long long)gm) - 1;
            gm &= gm - 1;
            float v = iou4(a, Wk->gbx[j]);
            if (v > mxv) { mxv = v; bj = j; }
        }
        Wk->smx[t] = mxv;
        Wk->sbest[t] = bj;
    }
    __syncthreads();

    // ---- sequential NMS + greedy matching (thread 0, bitmask) ----
    if (t == 0) {
        unsigned long long suppressed = 0;
        #pragma unroll 7
        for (int i = 0; i < NB; i++) {
            if (!((suppressed >> i) & 1ULL)) suppressed |= Wk->supm[i];
        }
        unsigned long long km = ~suppressed;
        keepm_s = km;
        unsigned long long matched = 0;
        for (int i = 0; i < NB; i++) {
            bool vp = (((km >> i) & 1ULL) != 0ULL) && (Wk->sconf[i] > 0.5f);
            int b = Wk->sbest[i];
            bool hit = vp && (Wk->smx[i] > 0.5f) && !((matched >> b) & 1ULL);
            if (hit) matched |= (1ULL << b);
            Wk->stp[i] = hit ? 1 : 0;
        }
    }
    __syncthreads();

    // ---- emit packed entry + per-image class counts ----
    if (t < NB) {
        bool vp = (((keepm_s >> t) & 1ULL) != 0ULL) && (Wk->sconf[t] > 0.5f);
        bool tp = Wk->stp[t] != 0;
        int sc = Wk->scls[t];
        unsigned v = (unsigned)sc
                   | (vp ? 32u : 0u)
                   | (tp ? 64u : 0u)
                   | (Wk->gvl[t] ? 128u : 0u)
                   | ((unsigned)Wk->gcl[t] << 8);
        g_entries[img * NB + t] = (unsigned short)v;
        if (vp) {
            if (tp) atomicAdd(&cnt_tp[sc], 1);
            else    atomicAdd(&cnt_fp[sc], 1);
        }
    }
    __syncthreads();

    if (t < NCLS) {
        int b = img >> 5;       // AP block index
        int a = cnt_tp[t], f = cnt_fp[t], g = cnt_gt[t];
        if (a) atomicAdd(&g_tp_part[t][b], a);
        if (f) atomicAdd(&g_fp_part[t][b], f);
        if (g) atomicAdd(&g_gt[t], g);
    }
}

// ---------------------------------------------------------------------------
// Kernel 2: exclusive prefix over the 128 block partials. 40 warps, one
// (class, tp|fp) pair each; 4 rounds of warp-scan.
// ---------------------------------------------------------------------------
__global__ __launch_bounds__(32) void k_scan() {
    int c = blockIdx.x % NCLS;
    int which = blockIdx.x / NCLS;
    int lane = threadIdx.x;
    int* arr = which ? g_fp_part[c] : g_tp_part[c];
    int acc = 0;
    #pragma unroll
    for (int ch = 0; ch < G / 32; ch++) {
        int x = arr[ch * 32 + lane];
        int orig = x;
        #pragma unroll
        for (int o = 1; o < 32; o <<= 1) {
            int y = __shfl_up_sync(0xffffffffu, x, o);
            if (lane >= o) x += y;
        }
        arr[ch * 32 + lane] = acc + x - orig;   // exclusive
        acc += __shfl_sync(0xffffffffu, x, 31);
    }
}

// ---------------------------------------------------------------------------
// Kernel 3: per-block AP contributions, fully parallel (hierarchical prefix).
// ---------------------------------------------------------------------------
__global__ __launch_bounds__(256) void k_apfinal() {
    int b = blockIdx.x, t = threadIdx.x;
    int lane = t & 31, w = t >> 5;

    __shared__ unsigned short se[EPB];        // 3136 B
    __shared__ int s_tpc[NSEG][NCLS];
    __shared__ int s_fpc[NSEG][NCLS];
    __shared__ float s_wsum[8];

    // stage entries (196 uint4 loads, coalesced)
    {
        const uint4* src = (const uint4*)(g_entries + b * EPB);
        uint4* d4 = (uint4*)se;
        if (t < EPB * 2 / 16) d4[t] = src[t];
    }
    // zero segment counters
    {
        int* z0 = &s_tpc[0][0];
        int* z1 = &s_fpc[0][0];
        for (int k = t; k < NSEG * NCLS; k += 256) { z0[k] = 0; z1[k] = 0; }
    }
    __syncthreads();

    // Phase A: per-segment per-class counts
    for (int e = t; e < EPB; e += 256) {
        unsigned v = se[e];
        if (v & 32u) {
            int s = e >> 5;
            int c = v & 31u;
            if (v & 64u) atomicAdd(&s_tpc[s][c], 1);
            else         atomicAdd(&s_fpc[s][c], 1);
        }
    }
    __syncthreads();

    // Phase B: exclusive scan over 49 segments per (class, tp|fp)
    if (t < NCLS * 2) {
        int c = t % NCLS;
        int* col0 = (t < NCLS) ? &s_tpc[0][c] : &s_fpc[0][c];
        int acc = 0;
        #pragma unroll
        for (int s = 0; s < NSEG; s++) {
            int* p = col0 + s * NCLS;
            int x = *p;
            *p = acc;
            acc += x;
        }
    }
    __syncthreads();

    // Phase C: within-segment prefix via match_any/ballot, sum TP contributions
    float acc = 0.0f;
    for (int s = w; s < NSEG; s += 8) {
        unsigned v = se[s * 32 + lane];
        bool valid = (v & 32u) != 0;
        int c = v & 31u;
        bool tp = (v & 64u) != 0;
        unsigned cc = valid ? (unsigned)c : 255u;
        unsigned peers = __match_any_sync(0xffffffffu, cc);
        unsigned tpb = __ballot_sync(0xffffffffu, tp);
        if (tp) {
            unsigned ltm = (1u << lane) - 1u;
            int Tw = __popc(peers & tpb & ltm);
            int Fw = __popc(peers & ltm) - Tw;
            int T = g_tp_part[c][b] + s_tpc[s][c] + Tw;
            int F = g_fp_part[c][b] + s_fpc[s][c] + Fw;
            float denr = (float)g_gt[c] + 1e-6f;
            bool first = (b == 0) && (s == 0) && (lane == 0);
            float p_prev = first ? 1.0f
                                 : (float)T / ((float)(T + F) + 1e-6f);
            float p_new = (float)(T + 1) / ((float)(T + 1 + F) + 1e-6f);
            acc += (1.0f / denr) * 0.5f * (p_prev + p_new);
        }
    }

    #pragma unroll
    for (int o = 16; o > 0; o >>= 1)
        acc += __shfl_xor_sync(0xffffffffu, acc, o);
    if (lane == 0) s_wsum[w] = acc;
    __syncthreads();
    if (t == 0) {
        float s = 0.0f;
        #pragma unroll
        for (int i = 0; i < 8; i++) s += s_wsum[i];
        g_ap_blk[b] = s;
    }
}

// ---------------------------------------------------------------------------
// Kernel 4: final reduction + divide; then re-zero accumulators for the next
// graph replay (invariant: every launch starts and ends with zeroed partials).
// ---------------------------------------------------------------------------
__global__ __launch_bounds__(128) void k_final(float* __restrict__ out) {
    int t = threadIdx.x;
    __shared__ float sv[G];
    sv[t] = g_ap_blk[t];
    __syncthreads();
    #pragma unroll
    for (int o = 64; o > 0; o >>= 1) {
        if (t < o) sv[t] += sv[t + o];
        __syncthreads();
    }
    if (t == 0) {
        int n = 0;
        #pragma unroll
        for (int c = 0; c < NCLS; c++) n += (g_gt[c] > 0);
        out[0] = sv[0] / fmaxf((float)n, 1.0f);
    }
    __syncthreads();   // everyone (esp. t==0) done reading accumulators
    int* tp0 = &g_tp_part[0][0];
    int* fp0 = &g_fp_part[0][0];
    for (int k = t; k < NCLS * G; k += 128) { tp0[k] = 0; fp0[k] = 0; }
    if (t < NCLS) g_gt[t] = 0;
}

extern "C" void kernel_launch(void* const* d_in, const int* in_sizes, int n_in,
                              void* d_out, int out_size) {
    const float* target = (const float*)d_in[0];
    const float* output = (const float*)d_in[1];
    float* out = (float*)d_out;

    k_per_image<<<BATCH, NTH>>>(target, output);
    k_scan<<<NCLS * 2, 32>>>();
    k_apfinal<<<G, 256>>>();
    k_final<<<1, 128>>>(out);
}

// round 7
// speedup vs baseline: 4.5450x; 1.1740x over previous
#include <cuda_runtime.h>
#include <cstdint>

#define S 7
#define NB 49            // S*S cells / boxes per image
#define BATCH 4096
#define NCLS 20
#define DEPTH 30         // B*5 + C
#define NTH 128
#define IPB 2            // images per block
#define NBLK (BATCH / IPB)   // 2048

#define TOTAL_E (BATCH * NB)      // 200704
#define G 128                     // AP blocks (4096/32 images)
#define EPB 1568                  // entries per AP block (32 images * 49)
#define NSEG 49                   // 32-entry segments per AP block

// Scratch (device globals; zero-init at load; k_final re-zeroes accumulators)
__device__ unsigned short g_entries[TOTAL_E];
__device__ int   g_tp_part[NCLS][G];   // raw per-AP-block counts
__device__ int   g_fp_part[NCLS][G];
__device__ float g_ap_blk[G];
__device__ int   g_gt[NCLS];

__device__ __forceinline__ float sigm(float x) {
    return 1.0f / (1.0f + expf(-x));
}

__device__ __forceinline__ float iou4(float4 a, float4 b) {
    float lx = fmaxf(a.x, b.x), ly = fmaxf(a.y, b.y);
    float rx = fminf(a.z, b.z), ry = fminf(a.w, b.w);
    float w = fmaxf(rx - lx, 0.0f), h = fmaxf(ry - ly, 0.0f);
    float inter = w * h;
    float aa = (a.z - a.x) * (a.w - a.y);
    float ab = (b.z - b.x) * (b.w - b.y);
    return inter / (aa + ab - inter);
}

// Working arrays overlaid on the staging buffer after both decodes complete.
struct __align__(16) Work {
    float4 ubox[NB];
    float4 gbx[NB];
    float4 sbox[NB];
    unsigned long long supm[NB];
    float uconf[NB];
    float sconf[NB];
    float smx[NB];
    int   ucls[NB];
    int   scls[NB];
    int   sbest[NB];
    int   gcl[NB];
    unsigned char gvl[NB];
    unsigned char stp[NB];
};

// ---------------------------------------------------------------------------
// Kernel 1: decode, sort, NMS, GT matching + count accumulation.
// Two images per block; sub-block li = t/64 owns image img0+li.
// ---------------------------------------------------------------------------
__global__ __launch_bounds__(NTH) void k_per_image(const float* __restrict__ target,
                                                   const float* __restrict__ output) {
    int img0 = blockIdx.x * IPB;
    int t = threadIdx.x;
    int li = t >> 6;          // 0 or 1: which image
    int tt = t & 63;          // thread within sub-block

    __shared__ __align__(16) float sbuf[IPB * NB * DEPTH];   // 11760 B staging, reused
    __shared__ unsigned long long gmask[IPB][NCLS];
    __shared__ unsigned long long pmask[IPB][NCLS];
    __shared__ int cnt_tp[IPB][NCLS], cnt_fp[IPB][NCLS], cnt_gt[IPB][NCLS];
    __shared__ unsigned long long keepm_s[IPB];

    if (t < IPB * NCLS) {
        int a = t / NCLS, c = t - a * NCLS;
        gmask[a][c] = 0ULL; pmask[a][c] = 0ULL;
        cnt_tp[a][c] = 0; cnt_fp[a][c] = 0; cnt_gt[a][c] = 0;
    }

    // ---- stage pred tensor for both images (contiguous, coalesced float2) ----
    {
        const float2* src = (const float2*)(output + (size_t)img0 * (NB * DEPTH));
        float2* dst = (float2*)sbuf;
        #pragma unroll 4
        for (int k = t; k < IPB * NB * DEPTH / 2; k += NTH) dst[k] = src[k];
    }
    __syncthreads();

    // ---- decode preds into registers ----
    float4 p_box = make_float4(0.f, 0.f, 0.f, 0.f);
    float  p_conf = 0.f;
    int    p_cls = 0;
    int iy = tt / S, jx = tt - iy * S;
    if (tt < NB) {
        const float* r = sbuf + (li * NB + tt) * DEPTH;
        float c0 = r[4], c1 = r[9];
        int resp = (c1 > c0) ? 1 : 0;
        float craw = resp ? c1 : c0;
        int cb = resp * 5;
        float x = sigm(r[cb + 0]);
        float y = sigm(r[cb + 1]);
        float w = sigm(r[cb + 2]);
        float h = sigm(r[cb + 3]);
        float cx = (x + (float)jx) * 64.0f;
        float cy = (y + (float)iy) * 64.0f;
        float W = w * 448.0f, H = h * 448.0f;
        p_box = make_float4(cx - 0.5f * W, cy - 0.5f * H, cx + 0.5f * W, cy + 0.5f * H);
        p_conf = sigm(craw);
        float bv = r[10];
        #pragma unroll
        for (int k = 1; k < NCLS; k++) {
            float v = r[10 + k];
            if (v > bv) { bv = v; p_cls = k; }
        }
    }
    __syncthreads();   // all pred-stage reads done

    // ---- stage GT tensor over same buffer ----
    {
        const float2* src = (const float2*)(target + (size_t)img0 * (NB * DEPTH));
        float2* dst = (float2*)sbuf;
        #pragma unroll 4
        for (int k = t; k < IPB * NB * DEPTH / 2; k += NTH) dst[k] = src[k];
    }
    __syncthreads();

    // ---- decode GT into registers ----
    float4 g_box = make_float4(0.f, 0.f, 0.f, 0.f);
    int g_cls = 0, g_valid = 0;
    if (tt < NB) {
        const float* g = sbuf + (li * NB + tt) * DEPTH;
        g_valid = (g[4] > 0.5f) ? 1 : 0;
        float cx = (g[0] + (float)jx) * 64.0f;
        float cy = (g[1] + (float)iy) * 64.0f;
        float W = g[2] * 448.0f, H = g[3] * 448.0f;
        g_box = make_float4(cx - 0.5f * W, cy - 0.5f * H, cx + 0.5f * W, cy + 0.5f * H);
        float bv = g[10];
        #pragma unroll
        for (int k = 1; k < NCLS; k++) {
            float v = g[10 + k];
            if (v > bv) { bv = v; g_cls = k; }
        }
    }
    __syncthreads();   // all GT-stage reads done -> safe to overlay

    Work* Wk = ((Work*)sbuf) + li;
    if (tt < NB) {
        Wk->ubox[tt] = p_box;
        Wk->uconf[tt] = p_conf;
        Wk->ucls[tt] = p_cls;
        Wk->gbx[tt] = g_box;
        Wk->gcl[tt] = g_cls;
        Wk->gvl[tt] = (unsigned char)g_valid;
        if (g_valid) {
            atomicOr(&gmask[li][g_cls], 1ULL << tt);
            atomicAdd(&cnt_gt[li][g_cls], 1);
        }
    }
    __syncthreads();

    // ---- stable descending rank-sort + per-class pred masks ----
    if (tt < NB) {
        float ci_c = Wk->uconf[tt];
        int rank = 0;
        #pragma unroll 7
        for (int j = 0; j < NB; j++) {
            float cj = Wk->uconf[j];
            rank += (cj > ci_c) || (cj == ci_c && j < tt);
        }
        Wk->sbox[rank] = Wk->ubox[tt];
        Wk->scls[rank] = Wk->ucls[tt];
        Wk->sconf[rank] = ci_c;
        atomicOr(&pmask[li][Wk->ucls[tt]], 1ULL << rank);
    }
    __syncthreads();

    // ---- suppression masks + best-GT via class bitmasks ----
    if (tt < NB) {
        float4 a = Wk->sbox[tt];
        int ci = Wk->scls[tt];

        unsigned long long m = 0;
        unsigned long long cand = pmask[li][ci] & (~0ULL << (tt + 1));   // tt<=48
        while (cand) {
            int j = __ffsll((long long)cand) - 1;
            cand &= cand - 1;
            if (iou4(a, Wk->sbox[j]) > 0.5f) m |= (1ULL << j);
        }
        Wk->supm[tt] = m;

        float mxv = -1.0f;
        int bj = 0;
        unsigned long long gm = gmask[li][ci];
        while (gm) {
            int j = __ffsll((long long)gm) - 1;
            gm &= gm - 1;
            float v = iou4(a, Wk->gbx[j]);
            if (v > mxv) { mxv = v; bj = j; }
        }
        Wk->smx[tt] = mxv;
        Wk->sbest[tt] = bj;
    }
    __syncthreads();

    // ---- sequential NMS + greedy matching (one thread per image, in parallel) ----
    if (tt == 0) {
        unsigned long long suppressed = 0;
        #pragma unroll 7
        for (int i = 0; i < NB; i++) {
            if (!((suppressed >> i) & 1ULL)) suppressed |= Wk->supm[i];
        }
        unsigned long long km = ~suppressed;
        keepm_s[li] = km;
        unsigned long long matched = 0;
        for (int i = 0; i < NB; i++) {
            bool vp = (((km >> i) & 1ULL) != 0ULL) && (Wk->sconf[i] > 0.5f);
            int b = Wk->sbest[i];
            bool hit = vp && (Wk->smx[i] > 0.5f) && !((matched >> b) & 1ULL);
            if (hit) matched |= (1ULL << b);
            Wk->stp[i] = hit ? 1 : 0;
        }
    }
    __syncthreads();

    // ---- emit packed entry + per-image class counts ----
    if (tt < NB) {
        bool vp = (((keepm_s[li] >> tt) & 1ULL) != 0ULL) && (Wk->sconf[tt] > 0.5f);
        bool tp = Wk->stp[tt] != 0;
        int sc = Wk->scls[tt];
        unsigned v = (unsigned)sc
                   | (vp ? 32u : 0u)
                   | (tp ? 64u : 0u)
                   | (Wk->gvl[tt] ? 128u : 0u)
                   | ((unsigned)Wk->gcl[tt] << 8);
        g_entries[(img0 + li) * NB + tt] = (unsigned short)v;
        if (vp) {
            if (tp) atomicAdd(&cnt_tp[li][sc], 1);
            else    atomicAdd(&cnt_fp[li][sc], 1);
        }
    }
    __syncthreads();

    if (tt < NCLS) {
        int b = (img0 + li) >> 5;       // AP block index (both images share it)
        int a = cnt_tp[li][tt], f = cnt_fp[li][tt], g = cnt_gt[li][tt];
        if (a) atomicAdd(&g_tp_part[tt][b], a);
        if (f) atomicAdd(&g_fp_part[tt][b], f);
        if (g) atomicAdd(&g_gt[tt], g);
    }
}

// ---------------------------------------------------------------------------
// Kernel 2: per-block AP contributions, fully parallel (hierarchical prefix).
// Computes its own exclusive block-prefix bases from raw partials.
// ---------------------------------------------------------------------------
__global__ __launch_bounds__(256) void k_apfinal() {
    int b = blockIdx.x, t = threadIdx.x;
    int lane = t & 31, w = t >> 5;

    __shared__ unsigned short se[EPB];        // 3136 B
    __shared__ int s_tpc[NSEG][NCLS];
    __shared__ int s_fpc[NSEG][NCLS];
    __shared__ int s_base[2][NCLS];           // [0]=tp base, [1]=fp base
    __shared__ float s_wsum[8];

    // stage entries (196 uint4 loads, coalesced)
    {
        const uint4* src = (const uint4*)(g_entries + b * EPB);
        uint4* d4 = (uint4*)se;
        if (t < EPB * 2 / 16) d4[t] = src[t];
    }
    // zero segment counters
    {
        int* z0 = &s_tpc[0][0];
        int* z1 = &s_fpc[0][0];
        for (int k = t; k < NSEG * NCLS; k += 256) { z0[k] = 0; z1[k] = 0; }
    }
    // exclusive block-prefix bases: 40 (class, tp|fp) pairs over 8 warps
    #pragma unroll
    for (int r = 0; r < 5; r++) {
        int pair = w * 5 + r;                 // 0..39
        int c = pair % NCLS;
        int which = pair / NCLS;
        const int* col = which ? g_fp_part[c] : g_tp_part[c];
        int sum = 0;
        #pragma unroll
        for (int ch = 0; ch < G / 32; ch++) {
            int idx = ch * 32 + lane;
            if (idx < b) sum += col[idx];
        }
        #pragma unroll
        for (int o = 16; o > 0; o >>= 1)
            sum += __shfl_xor_sync(0xffffffffu, sum, o);
        if (lane == 0) s_base[which][c] = sum;
    }
    __syncthreads();

    // Phase A: per-segment per-class counts
    for (int e = t; e < EPB; e += 256) {
        unsigned v = se[e];
        if (v & 32u) {
            int s = e >> 5;
            int c = v & 31u;
            if (v & 64u) atomicAdd(&s_tpc[s][c], 1);
            else         atomicAdd(&s_fpc[s][c], 1);
        }
    }
    __syncthreads();

    // Phase B: exclusive scan over 49 segments per (class, tp|fp)
    if (t < NCLS * 2) {
        int c = t % NCLS;
        int* col0 = (t < NCLS) ? &s_tpc[0][c] : &s_fpc[0][c];
        int acc = 0;
        #pragma unroll
        for (int s = 0; s < NSEG; s++) {
            int* p = col0 + s * NCLS;
            int x = *p;
            *p = acc;
            acc += x;
        }
    }
    __syncthreads();

    // Phase C: within-segment prefix via match_any/ballot, sum TP contributions
    float acc = 0.0f;
    for (int s = w; s < NSEG; s += 8) {
        unsigned v = se[s * 32 + lane];
        bool valid = (v & 32u) != 0;
        int c = v & 31u;
        bool tp = (v & 64u) != 0;
        unsigned cc = valid ? (unsigned)c : 255u;
        unsigned peers = __match_any_sync(0xffffffffu, cc);
        unsigned tpb = __ballot_sync(0xffffffffu, tp);
        if (tp) {
            unsigned ltm = (1u << lane) - 1u;
            int Tw = __popc(peers & tpb & ltm);
            int Fw = __popc(peers & ltm) - Tw;
            int T = s_base[0][c] + s_tpc[s][c] + Tw;
            int F = s_base[1][c] + s_fpc[s][c] + Fw;
            float denr = (float)g_gt[c] + 1e-6f;
            bool first = (b == 0) && (s == 0) && (lane == 0);
            float p_prev = first ? 1.0f
                                 : (float)T / ((float)(T + F) + 1e-6f);
            float p_new = (float)(T + 1) / ((float)(T + 1 + F) + 1e-6f);
            acc += (1.0f / denr) * 0.5f * (p_prev + p_new);
        }
    }

    #pragma unroll
    for (int o = 16; o > 0; o >>= 1)
        acc += __shfl_xor_sync(0xffffffffu, acc, o);
    if (lane == 0) s_wsum[w] = acc;
    __syncthreads();
    if (t == 0) {
        float s = 0.0f;
        #pragma unroll
        for (int i = 0; i < 8; i++) s += s_wsum[i];
        g_ap_blk[b] = s;
    }
}

// ---------------------------------------------------------------------------
// Kernel 3: final reduction + divide; re-zero accumulators for the next replay.
// ---------------------------------------------------------------------------
__global__ __launch_bounds__(256) void k_final(float* __restrict__ out) {
    int t = threadIdx.x;
    __shared__ float sv[G];
    if (t < G) sv[t] = g_ap_blk[t];
    __syncthreads();
    #pragma unroll
    for (int o = 64; o > 0; o >>= 1) {
        if (t < o && t + o < G) sv[t] += sv[t + o];
        __syncthreads();
    }
    if (t == 0) {
        int n = 0;
        #pragma unroll
        for (int c = 0; c < NCLS; c++) n += (g_gt[c] > 0);
        out[0] = sv[0] / fmaxf((float)n, 1.0f);
    }
    __syncthreads();   // t==0 done reading g_gt
    int* tp0 = &g_tp_part[0][0];
    int* fp0 = &g_fp_part[0][0];
    for (int k = t; k < NCLS * G; k += 256) { tp0[k] = 0; fp0[k] = 0; }
    if (t < NCLS) g_gt[t] = 0;
}

extern "C" void kernel_launch(void* const* d_in, const int* in_sizes, int n_in,
                              void* d_out, int out_size) {
    const float* target = (const float*)d_in[0];
    const float* output = (const float*)d_in[1];
    float* out = (float*)d_out;

    k_per_image<<<NBLK, NTH>>>(target, output);
    k_apfinal<<<G, 256>>>();
    k_final<<<1, 256>>>(out);
}